// round 6
// baseline (speedup 1.0000x reference)
#include <cuda_runtime.h>
#include <cuda_fp16.h>
#include <math_constants.h>

#define BATCH 1024
#define NGENE 8192
#define NSETS 2048
#define MAX_TOTAL 262144   // >= 2048 * 120

// Scratch (static device globals — no runtime allocation)
__device__ __half g_GT[NGENE * BATCH];    // transposed features, fp16, 16.8 MB
__device__ float  g_outT[NSETS * BATCH];  // set-major output staging, 8.4 MB
__device__ float  g_w[MAX_TOTAL];         // softmax weights per edge
__device__ int    g_off[NSETS + 1];       // segment start offsets

// ---------------------------------------------------------------------------
// K2: warp-per-segment softmax. Segment bounds found by binary search on the
// sorted segment_ids (replaces the old boundary-detect kernel); bounds are
// also published to g_off for k_agg.
// ---------------------------------------------------------------------------
__global__ void k_softmax(const float* __restrict__ logits,
                          const int* __restrict__ seg, int total) {
    int warp_id = (blockIdx.x * blockDim.x + threadIdx.x) >> 5;
    if (warp_id >= NSETS) return;
    int lane = threadIdx.x & 31;

    // lower_bound(seg, warp_id) and lower_bound(seg, warp_id+1)
    int lo = 0, hi = total;
    while (lo < hi) { int mid = (lo + hi) >> 1; if (seg[mid] < warp_id) lo = mid + 1; else hi = mid; }
    int beg = lo;
    hi = total;
    while (lo < hi) { int mid = (lo + hi) >> 1; if (seg[mid] < warp_id + 1) lo = mid + 1; else hi = mid; }
    int end = lo;

    if (lane == 0) {
        g_off[warp_id] = beg;
        if (warp_id == NSETS - 1) g_off[NSETS] = total;
    }

    float m = -CUDART_INF_F;
    for (int p = beg + lane; p < end; p += 32) m = fmaxf(m, logits[p]);
    #pragma unroll
    for (int o = 16; o; o >>= 1) m = fmaxf(m, __shfl_xor_sync(0xFFFFFFFFu, m, o));

    float sum = 0.0f;
    for (int p = beg + lane; p < end; p += 32) {
        float e = __expf(logits[p] - m);
        g_w[p] = e;
        sum += e;
    }
    #pragma unroll
    for (int o = 16; o; o >>= 1) sum += __shfl_xor_sync(0xFFFFFFFFu, sum, o);

    float inv = (sum > 0.0f) ? (1.0f / sum) : 0.0f;
    for (int p = beg + lane; p < end; p += 32) g_w[p] *= inv;
}

// ---------------------------------------------------------------------------
// K3: tiled transpose + fp16 convert: G(1024 x 8192) f32 -> GT(8192 x 1024) f16
// blockDim (32,8), grid (NGENE/32, BATCH/32)
// ---------------------------------------------------------------------------
__global__ void k_transpose(const float* __restrict__ G) {
    __shared__ float tile[32][33];
    int gx = blockIdx.x * 32;   // gene base
    int by = blockIdx.y * 32;   // batch base
    int x = gx + threadIdx.x;
    #pragma unroll
    for (int j = 0; j < 32; j += 8)
        tile[threadIdx.y + j][threadIdx.x] = G[(by + threadIdx.y + j) * NGENE + x];
    __syncthreads();
    #pragma unroll
    for (int j = 0; j < 32; j += 8)
        g_GT[(gx + threadIdx.y + j) * BATCH + by + threadIdx.x] =
            __float2half_rn(tile[threadIdx.x][threadIdx.y + j]);
}

// ---------------------------------------------------------------------------
// K4: aggregation, 2 sets per block (grid = NSETS/2, 256 threads).
// Half-block (128 threads) per set; thread lt owns batch rows 8*lt..8*lt+7
// via one uint4 (16B, 8 halfs) load per edge -> warp gather = 512B fully
// packed, double the in-flight bytes per load instruction vs round 5.
// Output rows are thread-contiguous: two adjacent float4 stores, set-major.
// ---------------------------------------------------------------------------
__global__ __launch_bounds__(256) void k_agg(const int* __restrict__ flat_idx) {
    int t    = threadIdx.x;
    int half = t >> 7;
    int lt   = t & 127;
    int s    = (blockIdx.x << 1) + half;

    __shared__ int   sh_idx[2][128];
    __shared__ float sh_w  [2][128];

    int beg = g_off[s];
    int n   = g_off[s + 1] - beg;
    if (n > 128) n = 128;             // structural: n <= 120
    if (lt < n) {
        sh_idx[half][lt] = flat_idx[beg + lt];
        sh_w  [half][lt] = g_w[beg + lt];
    }
    __syncthreads();

    const uint4* __restrict__ GT128 = reinterpret_cast<const uint4*>(g_GT);
    float4 a0 = make_float4(0.f, 0.f, 0.f, 0.f);
    float4 a1 = make_float4(0.f, 0.f, 0.f, 0.f);

    #pragma unroll 4
    for (int i = 0; i < n; i++) {
        float w = sh_w[half][i];
        uint4 u = GT128[sh_idx[half][i] * (BATCH / 8) + lt];
        float2 v;
        v = __half22float2(*reinterpret_cast<const __half2*>(&u.x));
        a0.x += w * v.x;  a0.y += w * v.y;
        v = __half22float2(*reinterpret_cast<const __half2*>(&u.y));
        a0.z += w * v.x;  a0.w += w * v.y;
        v = __half22float2(*reinterpret_cast<const __half2*>(&u.z));
        a1.x += w * v.x;  a1.y += w * v.y;
        v = __half22float2(*reinterpret_cast<const __half2*>(&u.w));
        a1.z += w * v.x;  a1.w += w * v.y;
    }

    float4* dst = reinterpret_cast<float4*>(g_outT + (size_t)s * BATCH) + 2 * lt;
    dst[0] = a0;
    dst[1] = a1;
}

// ---------------------------------------------------------------------------
// K5: transpose outT(2048 x 1024) -> out(1024 x 2048)
// blockDim (32,8), grid (BATCH/32, NSETS/32)
// ---------------------------------------------------------------------------
__global__ void k_out_transpose(float* __restrict__ out) {
    __shared__ float tile[32][33];
    int bx = blockIdx.x * 32;   // batch base
    int sy = blockIdx.y * 32;   // set base
    #pragma unroll
    for (int j = 0; j < 32; j += 8)
        tile[threadIdx.y + j][threadIdx.x] =
            g_outT[(size_t)(sy + threadIdx.y + j) * BATCH + bx + threadIdx.x];
    __syncthreads();
    #pragma unroll
    for (int j = 0; j < 32; j += 8)
        out[(size_t)(bx + threadIdx.y + j) * NSETS + sy + threadIdx.x] =
            tile[threadIdx.x][threadIdx.y + j];
}

// ---------------------------------------------------------------------------
// Launcher (graph-capturable: kernel launches only, default stream ordering)
// ---------------------------------------------------------------------------
extern "C" void kernel_launch(void* const* d_in, const int* in_sizes, int n_in,
                              void* d_out, int out_size) {
    const float* G      = (const float*)d_in[0];
    const float* logits = (const float*)d_in[1];
    const int*   fidx   = (const int*)d_in[2];
    const int*   seg    = (const int*)d_in[3];
    float*       out    = (float*)d_out;
    int total = in_sizes[1];

    k_softmax<<<(NSETS * 32 + 255) / 256, 256>>>(logits, seg, total);
    k_transpose<<<dim3(NGENE / 32, BATCH / 32), dim3(32, 8)>>>(G);
    k_agg<<<NSETS / 2, 256>>>(fidx);
    k_out_transpose<<<dim3(BATCH / 32, NSETS / 32), dim3(32, 8)>>>(out);
}